// round 2
// baseline (speedup 1.0000x reference)
#include <cuda_runtime.h>
#include <cuda_bf16.h>

// Problem constants
constexpr int Bb = 16384;
constexpr int Ss = 3;
constexpr int Dd = 512;
constexpr int Hh = 8;
constexpr int HDd = 64;
constexpr int FFf = 2048;
constexpr int Mm = Bb * Ss;  // 49152 tokens

// Scratch (device globals: allocation-free rule)
__device__ float g_X [Mm * Dd];        // stacked input + pos
__device__ float g_QKV[Mm * 3 * Dd];   // packed qkv
__device__ float g_O [Mm * Dd];        // attention output (pre-proj)
__device__ float g_Y1[Mm * Dd];        // x + attn_out (pre-LN1)
__device__ float g_X1[Mm * Dd];        // LN1 output
__device__ float g_H [Mm * FFf];       // relu(ff1)
__device__ float g_Y2[Mm * Dd];        // x1 + ff2 (pre-LN2)

// ---------------- f32x2 helpers ----------------
__device__ __forceinline__ void fma2(unsigned long long& acc,
                                     unsigned long long a,
                                     unsigned long long b) {
    asm("fma.rn.f32x2 %0, %1, %2, %0;" : "+l"(acc) : "l"(a), "l"(b));
}
__device__ __forceinline__ unsigned long long pack2(float lo, float hi) {
    unsigned long long r;
    asm("mov.b64 %0, {%1, %2};" : "=l"(r) : "f"(lo), "f"(hi));
    return r;
}
__device__ __forceinline__ void unpack2(unsigned long long v, float& lo, float& hi) {
    asm("mov.b64 {%0, %1}, %2;" : "=f"(lo), "=f"(hi) : "l"(v));
}

// ---------------- build X = stack(feat)+pos ----------------
__global__ void build_x_kernel(const float* __restrict__ f0,
                               const float* __restrict__ f1,
                               const float* __restrict__ f2,
                               const float* __restrict__ pos,
                               float* __restrict__ X) {
    int idx = blockIdx.x * blockDim.x + threadIdx.x;   // float4 index
    // total float4s = Mm*Dd/4 = 6291456
    int m  = idx >> 7;          // row (Dd/4 = 128 float4 per row)
    int c4 = idx & 127;         // float4 col
    int b  = m / 3;
    int s  = m - b * 3;
    const float* f = (s == 0) ? f0 : ((s == 1) ? f1 : f2);
    const float4 a = *reinterpret_cast<const float4*>(&f[b * Dd + c4 * 4]);
    const float4 p = *reinterpret_cast<const float4*>(&pos[s * Dd + c4 * 4]);
    float4 o;
    o.x = a.x + p.x; o.y = a.y + p.y; o.z = a.z + p.z; o.w = a.w + p.w;
    *reinterpret_cast<float4*>(&X[m * Dd + c4 * 4]) = o;
}

// ---------------- SGEMM: C[M,N] = A[M,K] * W[N,K]^T + bias (+R) (relu?) ----------------
// Tiles: BM=128, BN=128, BK=16; 256 threads; 8x8 per thread; f32x2 FMAs; double-buffered.
template <int N, int K, bool RELU, bool RESID>
__global__ __launch_bounds__(256, 2)
void sgemm_nt(const float* __restrict__ A, const float* __restrict__ W,
              const float* __restrict__ bias, const float* __restrict__ R,
              float* __restrict__ C) {
    constexpr int BM = 128, BN = 128, BK = 16;
    constexpr int KT = K / BK;

    __shared__ float As[2][BK][BM];
    __shared__ float Bs[2][BK][BN];

    const int tid = threadIdx.x;
    const int m0 = blockIdx.y * BM;
    const int n0 = blockIdx.x * BN;

    // compute mapping: 8 warps as 4x2, lanes as 4x8 -> 8x8 per thread
    const int warp = tid >> 5, lane = tid & 31;
    const int wm = warp >> 1, wn = warp & 1;
    const int lm = lane >> 3, ln = lane & 7;
    const int arow = wm * 32 + lm * 8;   // m offset in tile
    const int bcol = wn * 64 + ln * 8;   // n offset in tile

    // load mapping: 512 float4 per tile; thread loads ids {tid, tid+256}
    const int lrow = tid >> 2;           // 0..63 (second = +64)
    const int lk4  = (tid & 3) * 4;      // k sub-offset (0,4,8,12)

    const float* Ard = A + (size_t)(m0 + lrow) * K + lk4;
    const float* Wrd = W + (size_t)(n0 + lrow) * K + lk4;

    unsigned long long acc[8][4];
#pragma unroll
    for (int i = 0; i < 8; i++)
#pragma unroll
        for (int j = 0; j < 4; j++) acc[i][j] = 0ull;   // (+0.f,+0.f)

    // prefetch tile 0 -> smem buf 0
    {
        float4 a0 = *reinterpret_cast<const float4*>(Ard);
        float4 a1 = *reinterpret_cast<const float4*>(Ard + (size_t)64 * K);
        float4 b0 = *reinterpret_cast<const float4*>(Wrd);
        float4 b1 = *reinterpret_cast<const float4*>(Wrd + (size_t)64 * K);
        As[0][lk4 + 0][lrow] = a0.x; As[0][lk4 + 1][lrow] = a0.y;
        As[0][lk4 + 2][lrow] = a0.z; As[0][lk4 + 3][lrow] = a0.w;
        As[0][lk4 + 0][lrow + 64] = a1.x; As[0][lk4 + 1][lrow + 64] = a1.y;
        As[0][lk4 + 2][lrow + 64] = a1.z; As[0][lk4 + 3][lrow + 64] = a1.w;
        Bs[0][lk4 + 0][lrow] = b0.x; Bs[0][lk4 + 1][lrow] = b0.y;
        Bs[0][lk4 + 2][lrow] = b0.z; Bs[0][lk4 + 3][lrow] = b0.w;
        Bs[0][lk4 + 0][lrow + 64] = b1.x; Bs[0][lk4 + 1][lrow + 64] = b1.y;
        Bs[0][lk4 + 2][lrow + 64] = b1.z; Bs[0][lk4 + 3][lrow + 64] = b1.w;
    }
    __syncthreads();

    int buf = 0;
#pragma unroll 1
    for (int kk = 0; kk < KT; kk++) {
        float4 pa0, pa1, pb0, pb1;
        if (kk + 1 < KT) {
            const float* Ap = Ard + (size_t)(kk + 1) * BK;
            const float* Wp = Wrd + (size_t)(kk + 1) * BK;
            pa0 = *reinterpret_cast<const float4*>(Ap);
            pa1 = *reinterpret_cast<const float4*>(Ap + (size_t)64 * K);
            pb0 = *reinterpret_cast<const float4*>(Wp);
            pb1 = *reinterpret_cast<const float4*>(Wp + (size_t)64 * K);
        }

#pragma unroll
        for (int k = 0; k < BK; k++) {
            unsigned long long av[8], bv[4];
#pragma unroll
            for (int i = 0; i < 8; i++) {
                float a = As[buf][k][arow + i];
                av[i] = pack2(a, a);
            }
#pragma unroll
            for (int j = 0; j < 4; j++) {
                bv[j] = *reinterpret_cast<const unsigned long long*>(
                    &Bs[buf][k][bcol + 2 * j]);
            }
#pragma unroll
            for (int i = 0; i < 8; i++)
#pragma unroll
                for (int j = 0; j < 4; j++) fma2(acc[i][j], av[i], bv[j]);
        }

        if (kk + 1 < KT) {
            int nb = buf ^ 1;
            As[nb][lk4 + 0][lrow] = pa0.x; As[nb][lk4 + 1][lrow] = pa0.y;
            As[nb][lk4 + 2][lrow] = pa0.z; As[nb][lk4 + 3][lrow] = pa0.w;
            As[nb][lk4 + 0][lrow + 64] = pa1.x; As[nb][lk4 + 1][lrow + 64] = pa1.y;
            As[nb][lk4 + 2][lrow + 64] = pa1.z; As[nb][lk4 + 3][lrow + 64] = pa1.w;
            Bs[nb][lk4 + 0][lrow] = pb0.x; Bs[nb][lk4 + 1][lrow] = pb0.y;
            Bs[nb][lk4 + 2][lrow] = pb0.z; Bs[nb][lk4 + 3][lrow] = pb0.w;
            Bs[nb][lk4 + 0][lrow + 64] = pb1.x; Bs[nb][lk4 + 1][lrow + 64] = pb1.y;
            Bs[nb][lk4 + 2][lrow + 64] = pb1.z; Bs[nb][lk4 + 3][lrow + 64] = pb1.w;
            __syncthreads();
        }
        buf ^= 1;
    }

    // epilogue
#pragma unroll
    for (int i = 0; i < 8; i++) {
        const int row = m0 + arow + i;
#pragma unroll
        for (int j = 0; j < 4; j++) {
            const int col = n0 + bcol + 2 * j;
            float lo, hi;
            unpack2(acc[i][j], lo, hi);
            const float2 bb = *reinterpret_cast<const float2*>(&bias[col]);
            lo += bb.x; hi += bb.y;
            if (RESID) {
                const float2 rr = *reinterpret_cast<const float2*>(
                    &R[(size_t)row * N + col]);
                lo += rr.x; hi += rr.y;
            }
            if (RELU) { lo = fmaxf(lo, 0.f); hi = fmaxf(hi, 0.f); }
            float2 o; o.x = lo; o.y = hi;
            *reinterpret_cast<float2*>(&C[(size_t)row * N + col]) = o;
        }
    }
}

// ---------------- attention: one warp per (b,h) ----------------
__global__ void attn_kernel(const float* __restrict__ QKV, float* __restrict__ O) {
    const int warp = threadIdx.x >> 5;
    const int lane = threadIdx.x & 31;
    const int idx = blockIdx.x * 4 + warp;   // < Bb*Hh
    const int b = idx >> 3;
    const int h = idx & 7;

    float q[3][2], k[3][2], v[3][2];
#pragma unroll
    for (int s = 0; s < 3; s++) {
        const float* p = QKV + (size_t)(b * 3 + s) * (3 * Dd) + h * HDd;
        q[s][0] = p[lane];          q[s][1] = p[lane + 32];
        k[s][0] = p[Dd + lane];     k[s][1] = p[Dd + lane + 32];
        v[s][0] = p[2 * Dd + lane]; v[s][1] = p[2 * Dd + lane + 32];
    }

    float sc[3][3];
#pragma unroll
    for (int i = 0; i < 3; i++)
#pragma unroll
        for (int j = 0; j < 3; j++) {
            float p = q[i][0] * k[j][0] + q[i][1] * k[j][1];
#pragma unroll
            for (int off = 16; off > 0; off >>= 1)
                p += __shfl_xor_sync(0xFFFFFFFFu, p, off);
            sc[i][j] = p * 0.125f;   // 1/sqrt(64)
        }

#pragma unroll
    for (int i = 0; i < 3; i++) {
        const float mx = fmaxf(fmaxf(sc[i][0], sc[i][1]), sc[i][2]);
        const float e0 = expf(sc[i][0] - mx);
        const float e1 = expf(sc[i][1] - mx);
        const float e2 = expf(sc[i][2] - mx);
        const float inv = 1.f / (e0 + e1 + e2);
        const float a0 = e0 * inv, a1 = e1 * inv, a2 = e2 * inv;
        const float o0 = a0 * v[0][0] + a1 * v[1][0] + a2 * v[2][0];
        const float o1 = a0 * v[0][1] + a1 * v[1][1] + a2 * v[2][1];
        float* op = O + (size_t)(b * 3 + i) * Dd + h * HDd;
        op[lane] = o0;
        op[lane + 32] = o1;
    }
}

// ---------------- layernorm over D=512, one block(128) per row ----------------
__device__ __forceinline__ void block_stats(float s, float sq, int t,
                                            float* shs, float* shq,
                                            float& mu, float& rs) {
#pragma unroll
    for (int o = 16; o > 0; o >>= 1) {
        s  += __shfl_xor_sync(0xFFFFFFFFu, s, o);
        sq += __shfl_xor_sync(0xFFFFFFFFu, sq, o);
    }
    const int w = t >> 5;
    if ((t & 31) == 0) { shs[w] = s; shq[w] = sq; }
    __syncthreads();
    const float ts = shs[0] + shs[1] + shs[2] + shs[3];
    const float tq = shq[0] + shq[1] + shq[2] + shq[3];
    mu = ts * (1.f / 512.f);
    const float var = tq * (1.f / 512.f) - mu * mu;
    rs = rsqrtf(var + 1e-5f);
}

__global__ void ln_kernel(const float* __restrict__ Y,
                          const float* __restrict__ g,
                          const float* __restrict__ bta,
                          float* __restrict__ X) {
    const int row = blockIdx.x;
    const int t = threadIdx.x;   // 128
    __shared__ float shs[4], shq[4];
    const float4 v = *reinterpret_cast<const float4*>(&Y[(size_t)row * Dd + t * 4]);
    float mu, rs;
    block_stats(v.x + v.y + v.z + v.w,
                v.x * v.x + v.y * v.y + v.z * v.z + v.w * v.w,
                t, shs, shq, mu, rs);
    const float4 gg = *reinterpret_cast<const float4*>(&g[t * 4]);
    const float4 bb = *reinterpret_cast<const float4*>(&bta[t * 4]);
    float4 o;
    o.x = (v.x - mu) * rs * gg.x + bb.x;
    o.y = (v.y - mu) * rs * gg.y + bb.y;
    o.z = (v.z - mu) * rs * gg.z + bb.z;
    o.w = (v.w - mu) * rs * gg.w + bb.w;
    *reinterpret_cast<float4*>(&X[(size_t)row * Dd + t * 4]) = o;
}

// ---------------- LN2 + mean over S -> out[B,D], one block(128) per batch ----------------
__global__ void ln_mean_kernel(const float* __restrict__ Y,
                               const float* __restrict__ g,
                               const float* __restrict__ bta,
                               float* __restrict__ out) {
    const int b = blockIdx.x;
    const int t = threadIdx.x;
    __shared__ float shs[4], shq[4];
    const float4 gg = *reinterpret_cast<const float4*>(&g[t * 4]);
    const float4 bb = *reinterpret_cast<const float4*>(&bta[t * 4]);
    float4 accv = make_float4(0.f, 0.f, 0.f, 0.f);
#pragma unroll
    for (int s = 0; s < 3; s++) {
        const int row = b * 3 + s;
        const float4 v = *reinterpret_cast<const float4*>(&Y[(size_t)row * Dd + t * 4]);
        float mu, rs;
        block_stats(v.x + v.y + v.z + v.w,
                    v.x * v.x + v.y * v.y + v.z * v.z + v.w * v.w,
                    t, shs, shq, mu, rs);
        accv.x += (v.x - mu) * rs * gg.x + bb.x;
        accv.y += (v.y - mu) * rs * gg.y + bb.y;
        accv.z += (v.z - mu) * rs * gg.z + bb.z;
        accv.w += (v.w - mu) * rs * gg.w + bb.w;
        __syncthreads();   // protect shared stats for next s
    }
    const float inv3 = 1.f / 3.f;
    float4 o;
    o.x = accv.x * inv3; o.y = accv.y * inv3; o.z = accv.z * inv3; o.w = accv.w * inv3;
    *reinterpret_cast<float4*>(&out[(size_t)b * Dd + t * 4]) = o;
}

// ---------------- launch ----------------
extern "C" void kernel_launch(void* const* d_in, const int* in_sizes, int n_in,
                              void* d_out, int out_size) {
    const float* feat0 = (const float*)d_in[0];
    const float* feat1 = (const float*)d_in[1];
    const float* feat2 = (const float*)d_in[2];
    const float* pos   = (const float*)d_in[3];
    const float* w_in  = (const float*)d_in[4];
    const float* b_in  = (const float*)d_in[5];
    const float* w_out = (const float*)d_in[6];
    const float* b_out = (const float*)d_in[7];
    const float* ln1g  = (const float*)d_in[8];
    const float* ln1b  = (const float*)d_in[9];
    const float* w1    = (const float*)d_in[10];
    const float* b1    = (const float*)d_in[11];
    const float* w2    = (const float*)d_in[12];
    const float* b2    = (const float*)d_in[13];
    const float* ln2g  = (const float*)d_in[14];
    const float* ln2b  = (const float*)d_in[15];
    float* out = (float*)d_out;

    float *X, *QKV, *O, *Y1, *X1, *Hb, *Y2;
    cudaGetSymbolAddress((void**)&X,  g_X);
    cudaGetSymbolAddress((void**)&QKV, g_QKV);
    cudaGetSymbolAddress((void**)&O,  g_O);
    cudaGetSymbolAddress((void**)&Y1, g_Y1);
    cudaGetSymbolAddress((void**)&X1, g_X1);
    cudaGetSymbolAddress((void**)&Hb, g_H);
    cudaGetSymbolAddress((void**)&Y2, g_Y2);

    // 1. X = stack(feat0..2) + pos
    build_x_kernel<<<(Mm * Dd / 4) / 256, 256>>>(feat0, feat1, feat2, pos, X);

    // 2. QKV = X @ w_in^T + b_in            [M,1536]
    sgemm_nt<1536, 512, false, false><<<dim3(1536 / 128, Mm / 128), 256>>>(
        X, w_in, b_in, nullptr, QKV);

    // 3. attention -> O                     [M,512]
    attn_kernel<<<Bb * Hh / 4, 128>>>(QKV, O);

    // 4. Y1 = O @ w_out^T + b_out + X       [M,512]
    sgemm_nt<512, 512, false, true><<<dim3(512 / 128, Mm / 128), 256>>>(
        O, w_out, b_out, X, Y1);

    // 5. X1 = LN(Y1)
    ln_kernel<<<Mm, 128>>>(Y1, ln1g, ln1b, X1);

    // 6. H = relu(X1 @ w1^T + b1)           [M,2048]
    sgemm_nt<2048, 512, true, false><<<dim3(2048 / 128, Mm / 128), 256>>>(
        X1, w1, b1, nullptr, Hb);

    // 7. Y2 = H @ w2^T + b2 + X1            [M,512]
    sgemm_nt<512, 2048, false, true><<<dim3(512 / 128, Mm / 128), 256>>>(
        Hb, w2, b2, X1, Y2);

    // 8. out = mean_s LN(Y2)
    ln_mean_kernel<<<Bb, 128>>>(Y2, ln2g, ln2b, out);
}

// round 4
// speedup vs baseline: 2.2856x; 2.2856x over previous
#include <cuda_runtime.h>
#include <cuda_bf16.h>
#include <cstdint>

constexpr int Bb = 16384, Dd = 512, HDd = 64, FFf = 2048;
constexpr int Mm = Bb * 3;

// scratch
__device__ float g_X [Mm * Dd];
__device__ float g_QKV[(size_t)Mm * 3 * Dd];
__device__ float g_Y1[Mm * Dd];
__device__ float g_X1[Mm * Dd];
__device__ float g_Y2[Mm * Dd];
__device__ __nv_bfloat16 g_Xhi[Mm * Dd], g_Xlo[Mm * Dd];
__device__ __nv_bfloat16 g_Ohi[Mm * Dd], g_Olo[Mm * Dd];
__device__ __nv_bfloat16 g_X1hi[Mm * Dd], g_X1lo[Mm * Dd];
__device__ __nv_bfloat16 g_Hhi[(size_t)Mm * FFf], g_Hlo[(size_t)Mm * FFf];
__device__ __nv_bfloat16 g_Wihi[3 * Dd * Dd], g_Wilo[3 * Dd * Dd];
__device__ __nv_bfloat16 g_Wohi[Dd * Dd],     g_Wolo[Dd * Dd];
__device__ __nv_bfloat16 g_W1hi[FFf * Dd],    g_W1lo[FFf * Dd];
__device__ __nv_bfloat16 g_W2hi[Dd * FFf],    g_W2lo[Dd * FFf];

// ---- helpers ----
__device__ __forceinline__ uint32_t smem_u32(const void* p) {
    uint32_t a;
    asm("{ .reg .u64 t; cvta.to.shared.u64 t, %1; cvt.u32.u64 %0, t; }" : "=r"(a) : "l"(p));
    return a;
}
__device__ __forceinline__ void cp16(uint32_t s, const void* g) {
    asm volatile("cp.async.cg.shared.global [%0], [%1], 16;" :: "r"(s), "l"(g));
}
__device__ __forceinline__ void ldm_x4(uint32_t* r, uint32_t a) {
    asm volatile("ldmatrix.sync.aligned.m8n8.x4.shared.b16 {%0,%1,%2,%3}, [%4];"
                 : "=r"(r[0]), "=r"(r[1]), "=r"(r[2]), "=r"(r[3]) : "r"(a));
}
__device__ __forceinline__ void mma16816(float* c, const uint32_t* a,
                                         uint32_t b0, uint32_t b1) {
    asm volatile(
        "mma.sync.aligned.m16n8k16.row.col.f32.bf16.bf16.f32 "
        "{%0,%1,%2,%3}, {%4,%5,%6,%7}, {%8,%9}, {%0,%1,%2,%3};"
        : "+f"(c[0]), "+f"(c[1]), "+f"(c[2]), "+f"(c[3])
        : "r"(a[0]), "r"(a[1]), "r"(a[2]), "r"(a[3]), "r"(b0), "r"(b1));
}
// split float2 -> bf16 hi/lo pairs
__device__ __forceinline__ void split2(float x, float y,
                                       __nv_bfloat16* Hi, __nv_bfloat16* Lo, size_t off) {
    __nv_bfloat162 h = __floats2bfloat162_rn(x, y);
    float2 f = __bfloat1622float2(h);
    __nv_bfloat162 l = __floats2bfloat162_rn(x - f.x, y - f.y);
    *reinterpret_cast<__nv_bfloat162*>(Hi + off) = h;
    *reinterpret_cast<__nv_bfloat162*>(Lo + off) = l;
}
__device__ __forceinline__ void split4(float4 o, __nv_bfloat16* Hi, __nv_bfloat16* Lo,
                                       size_t off) {
    split2(o.x, o.y, Hi, Lo, off);
    split2(o.z, o.w, Hi, Lo, off + 2);
}

// ---- bf16x3 split mma.sync GEMM: C[M,N] = (Ahi+Alo)(Bhi+Blo)^T ----
// CTA 128x128, BK=32 bf16, 3-stage cp.async. 8 warps: wm=warp>>1 (32-row), wn=warp&1 (64-col).
// EPI: 0 = bias->f32 ; 1 = bias+resid->f32 ; 2 = bias+relu->bf16 hi/lo
constexpr int STG_BYTES = 20480;            // (128 A + 128 B) rows * 80B
constexpr int GEMM_SMEM = 3 * STG_BYTES;    // 61440

template <int K, int N, int EPI>
__global__ __launch_bounds__(256, 2)
void gemm_bf16x3(const __nv_bfloat16* __restrict__ Ahi, const __nv_bfloat16* __restrict__ Alo,
                 const __nv_bfloat16* __restrict__ Bhi, const __nv_bfloat16* __restrict__ Blo,
                 const float* __restrict__ bias, const float* __restrict__ resid,
                 float* __restrict__ Cf,
                 __nv_bfloat16* __restrict__ Chi, __nv_bfloat16* __restrict__ Clo) {
    extern __shared__ char sm_raw[];
    const uint32_t smb = smem_u32(sm_raw);

    const int tid = threadIdx.x, warp = tid >> 5, lane = tid & 31;
    const int m0 = blockIdx.y * 128, n0 = blockIdx.x * 128;
    const int wm = warp >> 1, wn = warp & 1;

    constexpr int NCH = K / 32;       // chunks per pass
    constexpr int NC = 3 * NCH;       // total chunks

    // load one k32 chunk into stage buffer (c % 3)
    auto load_chunk = [&](int c) {
        const int pass = c / NCH;
        const int kc = (c - pass * NCH) * 32;
        const __nv_bfloat16* A = (pass == 1) ? Alo : Ahi;
        const __nv_bfloat16* B = (pass == 2) ? Blo : Bhi;
        const uint32_t st = smb + (uint32_t)(c % 3) * STG_BYTES;
#pragma unroll
        for (int h = 0; h < 2; h++) {
            const int u = tid + h * 256;          // 0..511
            const int row = u >> 2, seg = u & 3;  // 128 rows x 4 x 16B
            cp16(st + row * 80 + seg * 16,
                 A + (size_t)(m0 + row) * K + kc + seg * 8);
            cp16(st + 10240 + row * 80 + seg * 16,
                 B + (size_t)(n0 + row) * K + kc + seg * 8);
        }
        asm volatile("cp.async.commit_group;");
    };

    float acc[2][8][4];
#pragma unroll
    for (int i = 0; i < 2; i++)
#pragma unroll
        for (int j = 0; j < 8; j++)
#pragma unroll
            for (int q = 0; q < 4; q++) acc[i][j][q] = 0.f;

    load_chunk(0);
    load_chunk(1);

#pragma unroll 1
    for (int c = 0; c < NC; c++) {
        if (c + 2 < NC) { asm volatile("cp.async.wait_group 1;" ::: "memory"); }
        else            { asm volatile("cp.async.wait_group 0;" ::: "memory"); }
        __syncthreads();
        if (c + 2 < NC) load_chunk(c + 2);

        const uint32_t Ab = smb + (uint32_t)(c % 3) * STG_BYTES;
        const uint32_t Bbs = Ab + 10240;
#pragma unroll
        for (int ks = 0; ks < 2; ks++) {
            uint32_t a[2][4], b[4][4];
#pragma unroll
            for (int mt = 0; mt < 2; mt++)
                ldm_x4(a[mt], Ab + (wm * 32 + mt * 16 + (lane & 15)) * 80
                              + ks * 32 + (lane >> 4) * 16);
#pragma unroll
            for (int nt = 0; nt < 4; nt++)
                ldm_x4(b[nt], Bbs + (wn * 64 + nt * 16 + (lane & 7) + ((lane >> 4) & 1) * 8) * 80
                              + ks * 32 + ((lane >> 3) & 1) * 16);
#pragma unroll
            for (int mt = 0; mt < 2; mt++)
#pragma unroll
                for (int nt = 0; nt < 4; nt++) {
                    mma16816(acc[mt][2 * nt],     a[mt], b[nt][0], b[nt][1]);
                    mma16816(acc[mt][2 * nt + 1], a[mt], b[nt][2], b[nt][3]);
                }
        }
    }

    // ---- epilogue: direct stores (4 lanes x 8B = 32B sectors) ----
#pragma unroll
    for (int mt = 0; mt < 2; mt++) {
        const int r0 = m0 + wm * 32 + mt * 16 + (lane >> 2);
#pragma unroll
        for (int nt = 0; nt < 8; nt++) {
            const int col = n0 + wn * 64 + nt * 8 + 2 * (lane & 3);
            const float2 bb = *reinterpret_cast<const float2*>(bias + col);
            float x0 = acc[mt][nt][0] + bb.x, y0 = acc[mt][nt][1] + bb.y;
            float x1 = acc[mt][nt][2] + bb.x, y1 = acc[mt][nt][3] + bb.y;
            const size_t o0 = (size_t)r0 * N + col;
            const size_t o1 = o0 + (size_t)8 * N;
            if (EPI == 1) {
                const float2 ra = *reinterpret_cast<const float2*>(resid + o0);
                const float2 rb = *reinterpret_cast<const float2*>(resid + o1);
                x0 += ra.x; y0 += ra.y; x1 += rb.x; y1 += rb.y;
            }
            if (EPI == 2) {
                x0 = fmaxf(x0, 0.f); y0 = fmaxf(y0, 0.f);
                x1 = fmaxf(x1, 0.f); y1 = fmaxf(y1, 0.f);
                split2(x0, y0, Chi, Clo, o0);
                split2(x1, y1, Chi, Clo, o1);
            } else {
                *reinterpret_cast<float2*>(Cf + o0) = make_float2(x0, y0);
                *reinterpret_cast<float2*>(Cf + o1) = make_float2(x1, y1);
            }
        }
    }
}

// ---- build X = stack(feat)+pos (+hi/lo) ----
__global__ void build_x_kernel(const float* __restrict__ f0, const float* __restrict__ f1,
                               const float* __restrict__ f2, const float* __restrict__ pos,
                               float* __restrict__ X,
                               __nv_bfloat16* __restrict__ Xhi, __nv_bfloat16* __restrict__ Xlo) {
    int idx = blockIdx.x * blockDim.x + threadIdx.x;
    int m = idx >> 7, c4 = idx & 127;
    int b = m / 3, s = m - b * 3;
    const float* f = (s == 0) ? f0 : ((s == 1) ? f1 : f2);
    const float4 a = *reinterpret_cast<const float4*>(&f[b * Dd + c4 * 4]);
    const float4 p = *reinterpret_cast<const float4*>(&pos[s * Dd + c4 * 4]);
    float4 o = make_float4(a.x + p.x, a.y + p.y, a.z + p.z, a.w + p.w);
    const size_t off = (size_t)m * Dd + c4 * 4;
    *reinterpret_cast<float4*>(&X[off]) = o;
    split4(o, Xhi, Xlo, off);
}

__global__ void conv_hilo(const float* __restrict__ s, __nv_bfloat16* __restrict__ hi,
                          __nv_bfloat16* __restrict__ lo, int n) {
    int i = blockIdx.x * 256 + threadIdx.x;
    if (i < n) {
        float x = s[i];
        __nv_bfloat16 h = __float2bfloat16(x);
        hi[i] = h;
        lo[i] = __float2bfloat16(x - __bfloat162float(h));
    }
}

// ---- attention: one warp per (b,h) ----
__global__ void attn_kernel(const float* __restrict__ QKV,
                            __nv_bfloat16* __restrict__ Ohi, __nv_bfloat16* __restrict__ Olo) {
    const int warp = threadIdx.x >> 5, lane = threadIdx.x & 31;
    const int idx = blockIdx.x * 4 + warp;
    const int b = idx >> 3, h = idx & 7;
    float q[3][2], k[3][2], v[3][2];
#pragma unroll
    for (int s = 0; s < 3; s++) {
        const float* p = QKV + (size_t)(b * 3 + s) * (3 * Dd) + h * HDd;
        q[s][0] = p[lane];          q[s][1] = p[lane + 32];
        k[s][0] = p[Dd + lane];     k[s][1] = p[Dd + lane + 32];
        v[s][0] = p[2*Dd + lane];   v[s][1] = p[2*Dd + lane + 32];
    }
    float sc[3][3];
#pragma unroll
    for (int i = 0; i < 3; i++)
#pragma unroll
        for (int j = 0; j < 3; j++) {
            float p = q[i][0] * k[j][0] + q[i][1] * k[j][1];
#pragma unroll
            for (int o = 16; o > 0; o >>= 1) p += __shfl_xor_sync(~0u, p, o);
            sc[i][j] = p * 0.125f;
        }
#pragma unroll
    for (int i = 0; i < 3; i++) {
        const float mx = fmaxf(fmaxf(sc[i][0], sc[i][1]), sc[i][2]);
        const float e0 = expf(sc[i][0]-mx), e1 = expf(sc[i][1]-mx), e2 = expf(sc[i][2]-mx);
        const float inv = 1.f / (e0 + e1 + e2);
        const float a0 = e0*inv, a1 = e1*inv, a2 = e2*inv;
        const float o0 = a0*v[0][0] + a1*v[1][0] + a2*v[2][0];
        const float o1 = a0*v[0][1] + a1*v[1][1] + a2*v[2][1];
        const size_t op = (size_t)(b * 3 + i) * Dd + h * HDd;
        __nv_bfloat16 h0 = __float2bfloat16(o0), h1 = __float2bfloat16(o1);
        Ohi[op + lane] = h0;      Ohi[op + lane + 32] = h1;
        Olo[op + lane] = __float2bfloat16(o0 - __bfloat162float(h0));
        Olo[op + lane + 32] = __float2bfloat16(o1 - __bfloat162float(h1));
    }
}

// ---- layernorm ----
__device__ __forceinline__ void block_stats(float s, float sq, int t, float* shs, float* shq,
                                            float& mu, float& rs) {
#pragma unroll
    for (int o = 16; o > 0; o >>= 1) {
        s += __shfl_xor_sync(~0u, s, o);
        sq += __shfl_xor_sync(~0u, sq, o);
    }
    const int w = t >> 5;
    if ((t & 31) == 0) { shs[w] = s; shq[w] = sq; }
    __syncthreads();
    const float ts = shs[0]+shs[1]+shs[2]+shs[3], tq = shq[0]+shq[1]+shq[2]+shq[3];
    mu = ts * (1.f/512.f);
    rs = rsqrtf(tq * (1.f/512.f) - mu*mu + 1e-5f);
}

__global__ void ln_kernel(const float* __restrict__ Y, const float* __restrict__ g,
                          const float* __restrict__ bta, float* __restrict__ X,
                          __nv_bfloat16* __restrict__ Xhi, __nv_bfloat16* __restrict__ Xlo) {
    const int row = blockIdx.x, t = threadIdx.x;
    __shared__ float shs[4], shq[4];
    const size_t off = (size_t)row * Dd + t * 4;
    const float4 v = *reinterpret_cast<const float4*>(&Y[off]);
    float mu, rs;
    block_stats(v.x+v.y+v.z+v.w, v.x*v.x+v.y*v.y+v.z*v.z+v.w*v.w, t, shs, shq, mu, rs);
    const float4 gg = *reinterpret_cast<const float4*>(&g[t*4]);
    const float4 bb = *reinterpret_cast<const float4*>(&bta[t*4]);
    float4 o;
    o.x = (v.x-mu)*rs*gg.x + bb.x; o.y = (v.y-mu)*rs*gg.y + bb.y;
    o.z = (v.z-mu)*rs*gg.z + bb.z; o.w = (v.w-mu)*rs*gg.w + bb.w;
    *reinterpret_cast<float4*>(&X[off]) = o;
    split4(o, Xhi, Xlo, off);
}

__global__ void ln_mean_kernel(const float* __restrict__ Y, const float* __restrict__ g,
                               const float* __restrict__ bta, float* __restrict__ out) {
    const int b = blockIdx.x, t = threadIdx.x;
    __shared__ float shs[4], shq[4];
    const float4 gg = *reinterpret_cast<const float4*>(&g[t*4]);
    const float4 bb = *reinterpret_cast<const float4*>(&bta[t*4]);
    float4 acc = make_float4(0.f, 0.f, 0.f, 0.f);
#pragma unroll
    for (int s = 0; s < 3; s++) {
        const float4 v = *reinterpret_cast<const float4*>(&Y[(size_t)(b*3+s)*Dd + t*4]);
        float mu, rs;
        block_stats(v.x+v.y+v.z+v.w, v.x*v.x+v.y*v.y+v.z*v.z+v.w*v.w, t, shs, shq, mu, rs);
        acc.x += (v.x-mu)*rs*gg.x + bb.x; acc.y += (v.y-mu)*rs*gg.y + bb.y;
        acc.z += (v.z-mu)*rs*gg.z + bb.z; acc.w += (v.w-mu)*rs*gg.w + bb.w;
        __syncthreads();
    }
    float4 o = make_float4(acc.x/3.f, acc.y/3.f, acc.z/3.f, acc.w/3.f);
    *reinterpret_cast<float4*>(&out[(size_t)b*Dd + t*4]) = o;
}

// ---- launch ----
extern "C" void kernel_launch(void* const* d_in, const int* in_sizes, int n_in,
                              void* d_out, int out_size) {
    const float* feat0 = (const float*)d_in[0];
    const float* feat1 = (const float*)d_in[1];
    const float* feat2 = (const float*)d_in[2];
    const float* pos   = (const float*)d_in[3];
    const float* w_in  = (const float*)d_in[4];
    const float* b_in  = (const float*)d_in[5];
    const float* w_out = (const float*)d_in[6];
    const float* b_out = (const float*)d_in[7];
    const float* ln1g  = (const float*)d_in[8];
    const float* ln1b  = (const float*)d_in[9];
    const float* w1    = (const float*)d_in[10];
    const float* b1    = (const float*)d_in[11];
    const float* w2    = (const float*)d_in[12];
    const float* b2    = (const float*)d_in[13];
    const float* ln2g  = (const float*)d_in[14];
    const float* ln2b  = (const float*)d_in[15];
    float* out = (float*)d_out;

    float *X, *QKV, *Y1, *X1, *Y2;
    __nv_bfloat16 *Xhi, *Xlo, *Ohi, *Olo, *X1hi, *X1lo, *Hhi, *Hlo;
    __nv_bfloat16 *Wihi, *Wilo, *Wohi, *Wolo, *W1hi, *W1lo, *W2hi, *W2lo;
    cudaGetSymbolAddress((void**)&X, g_X);     cudaGetSymbolAddress((void**)&QKV, g_QKV);
    cudaGetSymbolAddress((void**)&Y1, g_Y1);   cudaGetSymbolAddress((void**)&X1, g_X1);
    cudaGetSymbolAddress((void**)&Y2, g_Y2);
    cudaGetSymbolAddress((void**)&Xhi, g_Xhi);   cudaGetSymbolAddress((void**)&Xlo, g_Xlo);
    cudaGetSymbolAddress((void**)&Ohi, g_Ohi);   cudaGetSymbolAddress((void**)&Olo, g_Olo);
    cudaGetSymbolAddress((void**)&X1hi, g_X1hi); cudaGetSymbolAddress((void**)&X1lo, g_X1lo);
    cudaGetSymbolAddress((void**)&Hhi, g_Hhi);   cudaGetSymbolAddress((void**)&Hlo, g_Hlo);
    cudaGetSymbolAddress((void**)&Wihi, g_Wihi); cudaGetSymbolAddress((void**)&Wilo, g_Wilo);
    cudaGetSymbolAddress((void**)&Wohi, g_Wohi); cudaGetSymbolAddress((void**)&Wolo, g_Wolo);
    cudaGetSymbolAddress((void**)&W1hi, g_W1hi); cudaGetSymbolAddress((void**)&W1lo, g_W1lo);
    cudaGetSymbolAddress((void**)&W2hi, g_W2hi); cudaGetSymbolAddress((void**)&W2lo, g_W2lo);

    cudaFuncSetAttribute(gemm_bf16x3<512, 1536, 0>,
                         cudaFuncAttributeMaxDynamicSharedMemorySize, GEMM_SMEM);
    cudaFuncSetAttribute(gemm_bf16x3<512, 512, 1>,
                         cudaFuncAttributeMaxDynamicSharedMemorySize, GEMM_SMEM);
    cudaFuncSetAttribute(gemm_bf16x3<512, 2048, 2>,
                         cudaFuncAttributeMaxDynamicSharedMemorySize, GEMM_SMEM);
    cudaFuncSetAttribute(gemm_bf16x3<2048, 512, 1>,
                         cudaFuncAttributeMaxDynamicSharedMemorySize, GEMM_SMEM);

    conv_hilo<<<(3*Dd*Dd + 255)/256, 256>>>(w_in,  Wihi, Wilo, 3*Dd*Dd);
    conv_hilo<<<(Dd*Dd + 255)/256, 256>>>(w_out, Wohi, Wolo, Dd*Dd);
    conv_hilo<<<(FFf*Dd + 255)/256, 256>>>(w1, W1hi, W1lo, FFf*Dd);
    conv_hilo<<<(Dd*FFf + 255)/256, 256>>>(w2, W2hi, W2lo, Dd*FFf);

    build_x_kernel<<<(Mm*Dd/4)/256, 256>>>(feat0, feat1, feat2, pos, X, Xhi, Xlo);

    // QKV = X @ w_in^T + b_in
    gemm_bf16x3<512, 1536, 0><<<dim3(12, Mm/128), 256, GEMM_SMEM>>>(
        Xhi, Xlo, Wihi, Wilo, b_in, nullptr, QKV, nullptr, nullptr);

    attn_kernel<<<Bb*8/4, 128>>>(QKV, Ohi, Olo);

    // Y1 = O @ w_out^T + b_out + X
    gemm_bf16x3<512, 512, 1><<<dim3(4, Mm/128), 256, GEMM_SMEM>>>(
        Ohi, Olo, Wohi, Wolo, b_out, X, Y1, nullptr, nullptr);

    ln_kernel<<<Mm, 128>>>(Y1, ln1g, ln1b, X1, X1hi, X1lo);

    // H = relu(X1 @ w1^T + b1) -> bf16 hi/lo
    gemm_bf16x3<512, 2048, 2><<<dim3(16, Mm/128), 256, GEMM_SMEM>>>(
        X1hi, X1lo, W1hi, W1lo, b1, nullptr, nullptr, Hhi, Hlo);

    // Y2 = H @ w2^T + b2 + X1
    gemm_bf16x3<2048, 512, 1><<<dim3(4, Mm/128), 256, GEMM_SMEM>>>(
        Hhi, Hlo, W2hi, W2lo, b2, X1, Y2, nullptr, nullptr);

    ln_mean_kernel<<<Bb, 128>>>(Y2, ln2g, ln2b, out);
}

// round 5
// speedup vs baseline: 2.3798x; 1.0412x over previous
#include <cuda_runtime.h>
#include <cuda_bf16.h>
#include <cstdint>

constexpr int Bb = 16384, Dd = 512, HDd = 64, FFf = 2048;
constexpr int Mm = Bb * 3;

// scratch
__device__ float g_X [Mm * Dd];
__device__ float g_QKV[(size_t)Mm * 3 * Dd];
__device__ float g_Y1[Mm * Dd];
__device__ float g_X1[Mm * Dd];
__device__ float g_Y2[Mm * Dd];
__device__ __nv_bfloat16 g_Xhi[Mm * Dd], g_Xlo[Mm * Dd];
__device__ __nv_bfloat16 g_Ohi[Mm * Dd], g_Olo[Mm * Dd];
__device__ __nv_bfloat16 g_X1hi[Mm * Dd], g_X1lo[Mm * Dd];
__device__ __nv_bfloat16 g_Hhi[(size_t)Mm * FFf], g_Hlo[(size_t)Mm * FFf];
__device__ __nv_bfloat16 g_Wihi[3 * Dd * Dd], g_Wilo[3 * Dd * Dd];
__device__ __nv_bfloat16 g_Wohi[Dd * Dd],     g_Wolo[Dd * Dd];
__device__ __nv_bfloat16 g_W1hi[FFf * Dd],    g_W1lo[FFf * Dd];
__device__ __nv_bfloat16 g_W2hi[Dd * FFf],    g_W2lo[Dd * FFf];

// ---- helpers ----
__device__ __forceinline__ uint32_t smem_u32(const void* p) {
    uint32_t a;
    asm("{ .reg .u64 t; cvta.to.shared.u64 t, %1; cvt.u32.u64 %0, t; }" : "=r"(a) : "l"(p));
    return a;
}
__device__ __forceinline__ void cp16(uint32_t s, const void* g) {
    asm volatile("cp.async.cg.shared.global [%0], [%1], 16;" :: "r"(s), "l"(g));
}
__device__ __forceinline__ void ldm_x4(uint32_t* r, uint32_t a) {
    asm volatile("ldmatrix.sync.aligned.m8n8.x4.shared.b16 {%0,%1,%2,%3}, [%4];"
                 : "=r"(r[0]), "=r"(r[1]), "=r"(r[2]), "=r"(r[3]) : "r"(a));
}
__device__ __forceinline__ void mma16816(float* c, const uint32_t* a,
                                         uint32_t b0, uint32_t b1) {
    asm volatile(
        "mma.sync.aligned.m16n8k16.row.col.f32.bf16.bf16.f32 "
        "{%0,%1,%2,%3}, {%4,%5,%6,%7}, {%8,%9}, {%0,%1,%2,%3};"
        : "+f"(c[0]), "+f"(c[1]), "+f"(c[2]), "+f"(c[3])
        : "r"(a[0]), "r"(a[1]), "r"(a[2]), "r"(a[3]), "r"(b0), "r"(b1));
}
__device__ __forceinline__ void split2(float x, float y,
                                       __nv_bfloat16* Hi, __nv_bfloat16* Lo, size_t off) {
    __nv_bfloat162 h = __floats2bfloat162_rn(x, y);
    float2 f = __bfloat1622float2(h);
    __nv_bfloat162 l = __floats2bfloat162_rn(x - f.x, y - f.y);
    *reinterpret_cast<__nv_bfloat162*>(Hi + off) = h;
    *reinterpret_cast<__nv_bfloat162*>(Lo + off) = l;
}
__device__ __forceinline__ void split4(float4 o, __nv_bfloat16* Hi, __nv_bfloat16* Lo,
                                       size_t off) {
    split2(o.x, o.y, Hi, Lo, off);
    split2(o.z, o.w, Hi, Lo, off + 2);
}

// ---- merged bf16x3 split mma.sync GEMM: C = (Ahi+Alo)(Bhi+Blo)^T (drop lo*lo) ----
// CTA 256x128, 256 threads, 8 warps (wm 0..3 x wn 0..1), warp tile 64x64, BK=32,
// 3-stage cp.async; per chunk loads Ahi/Alo/Bhi/Blo once and runs 3 MMA passes with
// register fragment reuse.
// EPI: 0 = bias->f32 ; 1 = bias+resid->f32 ; 2 = bias+relu->bf16 hi/lo
constexpr int STG_BYTES = 61440;            // Ahi 20480 | Alo 20480 | Bhi 10240 | Blo 10240
constexpr int GEMM_SMEM = 3 * STG_BYTES;    // 184320

template <int K, int N, int EPI>
__global__ __launch_bounds__(256, 1)
void gemm_bf16x3(const __nv_bfloat16* __restrict__ Ahi, const __nv_bfloat16* __restrict__ Alo,
                 const __nv_bfloat16* __restrict__ Bhi, const __nv_bfloat16* __restrict__ Blo,
                 const float* __restrict__ bias, const float* __restrict__ resid,
                 float* __restrict__ Cf,
                 __nv_bfloat16* __restrict__ Chi, __nv_bfloat16* __restrict__ Clo) {
    extern __shared__ char sm_raw[];
    const uint32_t smb = smem_u32(sm_raw);

    const int tid = threadIdx.x, warp = tid >> 5, lane = tid & 31;
    const int m0 = blockIdx.y * 256, n0 = blockIdx.x * 128;
    const int wm = warp >> 1, wn = warp & 1;

    constexpr int NC = K / 32;

    auto load_chunk = [&](int c) {
        const int kc = c * 32;
        const uint32_t st = smb + (uint32_t)(c % 3) * STG_BYTES;
#pragma unroll
        for (int i = 0; i < 4; i++) {
            const int u = tid + i * 256;           // 0..1023: 256 rows x 4 segs
            const int row = u >> 2, seg = u & 3;
            const size_t go = (size_t)(m0 + row) * K + kc + seg * 8;
            const uint32_t so = st + row * 80 + seg * 16;
            cp16(so, Ahi + go);
            cp16(so + 20480, Alo + go);
        }
#pragma unroll
        for (int i = 0; i < 2; i++) {
            const int u = tid + i * 256;           // 0..511: 128 rows x 4 segs
            const int row = u >> 2, seg = u & 3;
            const size_t go = (size_t)(n0 + row) * K + kc + seg * 8;
            const uint32_t so = st + 40960 + row * 80 + seg * 16;
            cp16(so, Bhi + go);
            cp16(so + 10240, Blo + go);
        }
        asm volatile("cp.async.commit_group;");
    };

    float acc[4][8][4];
#pragma unroll
    for (int i = 0; i < 4; i++)
#pragma unroll
        for (int j = 0; j < 8; j++)
#pragma unroll
            for (int q = 0; q < 4; q++) acc[i][j][q] = 0.f;

    load_chunk(0);
    load_chunk(1);

    // per-lane ldmatrix address components (constant across chunks)
    const uint32_t a_off = (uint32_t)(wm * 64 + (lane & 15)) * 80 + (lane >> 4) * 16;
    const uint32_t b_off = (uint32_t)(wn * 64 + (lane & 7) + ((lane >> 4) & 1) * 8) * 80
                           + ((lane >> 3) & 1) * 16;

#pragma unroll 1
    for (int c = 0; c < NC; c++) {
        if (c + 2 < NC) { asm volatile("cp.async.wait_group 1;" ::: "memory"); }
        else            { asm volatile("cp.async.wait_group 0;" ::: "memory"); }
        __syncthreads();
        if (c + 2 < NC) load_chunk(c + 2);

        const uint32_t st = smb + (uint32_t)(c % 3) * STG_BYTES;
#pragma unroll
        for (int ks = 0; ks < 2; ks++) {
            uint32_t ah[4][4], bh[4][4], t[4][4];
            // pass 1 fragments
#pragma unroll
            for (int mt = 0; mt < 4; mt++)
                ldm_x4(ah[mt], st + a_off + (uint32_t)mt * (16 * 80) + ks * 32);
#pragma unroll
            for (int nt = 0; nt < 4; nt++)
                ldm_x4(bh[nt], st + 40960 + b_off + (uint32_t)nt * (16 * 80) + ks * 32);
#pragma unroll
            for (int mt = 0; mt < 4; mt++)
#pragma unroll
                for (int nt = 0; nt < 4; nt++) {
                    mma16816(acc[mt][2 * nt],     ah[mt], bh[nt][0], bh[nt][1]);
                    mma16816(acc[mt][2 * nt + 1], ah[mt], bh[nt][2], bh[nt][3]);
                }
            // pass 2: Alo x Bhi (reuse bh)
#pragma unroll
            for (int mt = 0; mt < 4; mt++)
                ldm_x4(t[mt], st + 20480 + a_off + (uint32_t)mt * (16 * 80) + ks * 32);
#pragma unroll
            for (int mt = 0; mt < 4; mt++)
#pragma unroll
                for (int nt = 0; nt < 4; nt++) {
                    mma16816(acc[mt][2 * nt],     t[mt], bh[nt][0], bh[nt][1]);
                    mma16816(acc[mt][2 * nt + 1], t[mt], bh[nt][2], bh[nt][3]);
                }
            // pass 3: Ahi x Blo (reuse ah, overwrite t with Blo)
#pragma unroll
            for (int nt = 0; nt < 4; nt++)
                ldm_x4(t[nt], st + 51200 + b_off + (uint32_t)nt * (16 * 80) + ks * 32);
#pragma unroll
            for (int mt = 0; mt < 4; mt++)
#pragma unroll
                for (int nt = 0; nt < 4; nt++) {
                    mma16816(acc[mt][2 * nt],     ah[mt], t[nt][0], t[nt][1]);
                    mma16816(acc[mt][2 * nt + 1], ah[mt], t[nt][2], t[nt][3]);
                }
        }
    }

    // ---- epilogue ----
#pragma unroll
    for (int mt = 0; mt < 4; mt++) {
        const int r0 = m0 + wm * 64 + mt * 16 + (lane >> 2);
#pragma unroll
        for (int nt = 0; nt < 8; nt++) {
            const int col = n0 + wn * 64 + nt * 8 + 2 * (lane & 3);
            const float2 bb = *reinterpret_cast<const float2*>(bias + col);
            float x0 = acc[mt][nt][0] + bb.x, y0 = acc[mt][nt][1] + bb.y;
            float x1 = acc[mt][nt][2] + bb.x, y1 = acc[mt][nt][3] + bb.y;
            const size_t o0 = (size_t)r0 * N + col;
            const size_t o1 = o0 + (size_t)8 * N;
            if (EPI == 1) {
                const float2 ra = *reinterpret_cast<const float2*>(resid + o0);
                const float2 rb = *reinterpret_cast<const float2*>(resid + o1);
                x0 += ra.x; y0 += ra.y; x1 += rb.x; y1 += rb.y;
            }
            if (EPI == 2) {
                x0 = fmaxf(x0, 0.f); y0 = fmaxf(y0, 0.f);
                x1 = fmaxf(x1, 0.f); y1 = fmaxf(y1, 0.f);
                split2(x0, y0, Chi, Clo, o0);
                split2(x1, y1, Chi, Clo, o1);
            } else {
                *reinterpret_cast<float2*>(Cf + o0) = make_float2(x0, y0);
                *reinterpret_cast<float2*>(Cf + o1) = make_float2(x1, y1);
            }
        }
    }
}

// ---- build X = stack(feat)+pos (+hi/lo) ----
__global__ void build_x_kernel(const float* __restrict__ f0, const float* __restrict__ f1,
                               const float* __restrict__ f2, const float* __restrict__ pos,
                               float* __restrict__ X,
                               __nv_bfloat16* __restrict__ Xhi, __nv_bfloat16* __restrict__ Xlo) {
    int idx = blockIdx.x * blockDim.x + threadIdx.x;
    int m = idx >> 7, c4 = idx & 127;
    int b = m / 3, s = m - b * 3;
    const float* f = (s == 0) ? f0 : ((s == 1) ? f1 : f2);
    const float4 a = *reinterpret_cast<const float4*>(&f[b * Dd + c4 * 4]);
    const float4 p = *reinterpret_cast<const float4*>(&pos[s * Dd + c4 * 4]);
    float4 o = make_float4(a.x + p.x, a.y + p.y, a.z + p.z, a.w + p.w);
    const size_t off = (size_t)m * Dd + c4 * 4;
    *reinterpret_cast<float4*>(&X[off]) = o;
    split4(o, Xhi, Xlo, off);
}

__global__ void conv_hilo(const float* __restrict__ s, __nv_bfloat16* __restrict__ hi,
                          __nv_bfloat16* __restrict__ lo, int n) {
    int i = blockIdx.x * 256 + threadIdx.x;
    if (i < n) {
        float x = s[i];
        __nv_bfloat16 h = __float2bfloat16(x);
        hi[i] = h;
        lo[i] = __float2bfloat16(x - __bfloat162float(h));
    }
}

// ---- attention: one warp per (b,h) ----
__global__ void attn_kernel(const float* __restrict__ QKV,
                            __nv_bfloat16* __restrict__ Ohi, __nv_bfloat16* __restrict__ Olo) {
    const int warp = threadIdx.x >> 5, lane = threadIdx.x & 31;
    const int idx = blockIdx.x * 4 + warp;
    const int b = idx >> 3, h = idx & 7;
    float q[3][2], k[3][2], v[3][2];
#pragma unroll
    for (int s = 0; s < 3; s++) {
        const float* p = QKV + (size_t)(b * 3 + s) * (3 * Dd) + h * HDd;
        q[s][0] = p[lane];          q[s][1] = p[lane + 32];
        k[s][0] = p[Dd + lane];     k[s][1] = p[Dd + lane + 32];
        v[s][0] = p[2*Dd + lane];   v[s][1] = p[2*Dd + lane + 32];
    }
    float sc[3][3];
#pragma unroll
    for (int i = 0; i < 3; i++)
#pragma unroll
        for (int j = 0; j < 3; j++) {
            float p = q[i][0] * k[j][0] + q[i][1] * k[j][1];
#pragma unroll
            for (int o = 16; o > 0; o >>= 1) p += __shfl_xor_sync(~0u, p, o);
            sc[i][j] = p * 0.125f;
        }
#pragma unroll
    for (int i = 0; i < 3; i++) {
        const float mx = fmaxf(fmaxf(sc[i][0], sc[i][1]), sc[i][2]);
        const float e0 = expf(sc[i][0]-mx), e1 = expf(sc[i][1]-mx), e2 = expf(sc[i][2]-mx);
        const float inv = 1.f / (e0 + e1 + e2);
        const float a0 = e0*inv, a1 = e1*inv, a2 = e2*inv;
        const float o0 = a0*v[0][0] + a1*v[1][0] + a2*v[2][0];
        const float o1 = a0*v[0][1] + a1*v[1][1] + a2*v[2][1];
        const size_t op = (size_t)(b * 3 + i) * Dd + h * HDd;
        __nv_bfloat16 h0 = __float2bfloat16(o0), h1 = __float2bfloat16(o1);
        Ohi[op + lane] = h0;      Ohi[op + lane + 32] = h1;
        Olo[op + lane] = __float2bfloat16(o0 - __bfloat162float(h0));
        Olo[op + lane + 32] = __float2bfloat16(o1 - __bfloat162float(h1));
    }
}

// ---- layernorm ----
__device__ __forceinline__ void block_stats(float s, float sq, int t, float* shs, float* shq,
                                            float& mu, float& rs) {
#pragma unroll
    for (int o = 16; o > 0; o >>= 1) {
        s += __shfl_xor_sync(~0u, s, o);
        sq += __shfl_xor_sync(~0u, sq, o);
    }
    const int w = t >> 5;
    if ((t & 31) == 0) { shs[w] = s; shq[w] = sq; }
    __syncthreads();
    const float ts = shs[0]+shs[1]+shs[2]+shs[3], tq = shq[0]+shq[1]+shq[2]+shq[3];
    mu = ts * (1.f/512.f);
    rs = rsqrtf(tq * (1.f/512.f) - mu*mu + 1e-5f);
}

__global__ void ln_kernel(const float* __restrict__ Y, const float* __restrict__ g,
                          const float* __restrict__ bta, float* __restrict__ X,
                          __nv_bfloat16* __restrict__ Xhi, __nv_bfloat16* __restrict__ Xlo) {
    const int row = blockIdx.x, t = threadIdx.x;
    __shared__ float shs[4], shq[4];
    const size_t off = (size_t)row * Dd + t * 4;
    const float4 v = *reinterpret_cast<const float4*>(&Y[off]);
    float mu, rs;
    block_stats(v.x+v.y+v.z+v.w, v.x*v.x+v.y*v.y+v.z*v.z+v.w*v.w, t, shs, shq, mu, rs);
    const float4 gg = *reinterpret_cast<const float4*>(&g[t*4]);
    const float4 bb = *reinterpret_cast<const float4*>(&bta[t*4]);
    float4 o;
    o.x = (v.x-mu)*rs*gg.x + bb.x; o.y = (v.y-mu)*rs*gg.y + bb.y;
    o.z = (v.z-mu)*rs*gg.z + bb.z; o.w = (v.w-mu)*rs*gg.w + bb.w;
    *reinterpret_cast<float4*>(&X[off]) = o;
    split4(o, Xhi, Xlo, off);
}

__global__ void ln_mean_kernel(const float* __restrict__ Y, const float* __restrict__ g,
                               const float* __restrict__ bta, float* __restrict__ out) {
    const int b = blockIdx.x, t = threadIdx.x;
    __shared__ float shs[4], shq[4];
    const float4 gg = *reinterpret_cast<const float4*>(&g[t*4]);
    const float4 bb = *reinterpret_cast<const float4*>(&bta[t*4]);
    float4 acc = make_float4(0.f, 0.f, 0.f, 0.f);
#pragma unroll
    for (int s = 0; s < 3; s++) {
        const float4 v = *reinterpret_cast<const float4*>(&Y[(size_t)(b*3+s)*Dd + t*4]);
        float mu, rs;
        block_stats(v.x+v.y+v.z+v.w, v.x*v.x+v.y*v.y+v.z*v.z+v.w*v.w, t, shs, shq, mu, rs);
        acc.x += (v.x-mu)*rs*gg.x + bb.x; acc.y += (v.y-mu)*rs*gg.y + bb.y;
        acc.z += (v.z-mu)*rs*gg.z + bb.z; acc.w += (v.w-mu)*rs*gg.w + bb.w;
        __syncthreads();
    }
    float4 o = make_float4(acc.x/3.f, acc.y/3.f, acc.z/3.f, acc.w/3.f);
    *reinterpret_cast<float4*>(&out[(size_t)b*Dd + t*4]) = o;
}

// ---- launch ----
extern "C" void kernel_launch(void* const* d_in, const int* in_sizes, int n_in,
                              void* d_out, int out_size) {
    const float* feat0 = (const float*)d_in[0];
    const float* feat1 = (const float*)d_in[1];
    const float* feat2 = (const float*)d_in[2];
    const float* pos   = (const float*)d_in[3];
    const float* w_in  = (const float*)d_in[4];
    const float* b_in  = (const float*)d_in[5];
    const float* w_out = (const float*)d_in[6];
    const float* b_out = (const float*)d_in[7];
    const float* ln1g  = (const float*)d_in[8];
    const float* ln1b  = (const float*)d_in[9];
    const float* w1    = (const float*)d_in[10];
    const float* b1    = (const float*)d_in[11];
    const float* w2    = (const float*)d_in[12];
    const float* b2    = (const float*)d_in[13];
    const float* ln2g  = (const float*)d_in[14];
    const float* ln2b  = (const float*)d_in[15];
    float* out = (float*)d_out;

    float *X, *QKV, *Y1, *X1, *Y2;
    __nv_bfloat16 *Xhi, *Xlo, *Ohi, *Olo, *X1hi, *X1lo, *Hhi, *Hlo;
    __nv_bfloat16 *Wihi, *Wilo, *Wohi, *Wolo, *W1hi, *W1lo, *W2hi, *W2lo;
    cudaGetSymbolAddress((void**)&X, g_X);     cudaGetSymbolAddress((void**)&QKV, g_QKV);
    cudaGetSymbolAddress((void**)&Y1, g_Y1);   cudaGetSymbolAddress((void**)&X1, g_X1);
    cudaGetSymbolAddress((void**)&Y2, g_Y2);
    cudaGetSymbolAddress((void**)&Xhi, g_Xhi);   cudaGetSymbolAddress((void**)&Xlo, g_Xlo);
    cudaGetSymbolAddress((void**)&Ohi, g_Ohi);   cudaGetSymbolAddress((void**)&Olo, g_Olo);
    cudaGetSymbolAddress((void**)&X1hi, g_X1hi); cudaGetSymbolAddress((void**)&X1lo, g_X1lo);
    cudaGetSymbolAddress((void**)&Hhi, g_Hhi);   cudaGetSymbolAddress((void**)&Hlo, g_Hlo);
    cudaGetSymbolAddress((void**)&Wihi, g_Wihi); cudaGetSymbolAddress((void**)&Wilo, g_Wilo);
    cudaGetSymbolAddress((void**)&Wohi, g_Wohi); cudaGetSymbolAddress((void**)&Wolo, g_Wolo);
    cudaGetSymbolAddress((void**)&W1hi, g_W1hi); cudaGetSymbolAddress((void**)&W1lo, g_W1lo);
    cudaGetSymbolAddress((void**)&W2hi, g_W2hi); cudaGetSymbolAddress((void**)&W2lo, g_W2lo);

    cudaFuncSetAttribute(gemm_bf16x3<512, 1536, 0>,
                         cudaFuncAttributeMaxDynamicSharedMemorySize, GEMM_SMEM);
    cudaFuncSetAttribute(gemm_bf16x3<512, 512, 1>,
                         cudaFuncAttributeMaxDynamicSharedMemorySize, GEMM_SMEM);
    cudaFuncSetAttribute(gemm_bf16x3<512, 2048, 2>,
                         cudaFuncAttributeMaxDynamicSharedMemorySize, GEMM_SMEM);
    cudaFuncSetAttribute(gemm_bf16x3<2048, 512, 1>,
                         cudaFuncAttributeMaxDynamicSharedMemorySize, GEMM_SMEM);

    conv_hilo<<<(3*Dd*Dd + 255)/256, 256>>>(w_in,  Wihi, Wilo, 3*Dd*Dd);
    conv_hilo<<<(Dd*Dd + 255)/256, 256>>>(w_out, Wohi, Wolo, Dd*Dd);
    conv_hilo<<<(FFf*Dd + 255)/256, 256>>>(w1, W1hi, W1lo, FFf*Dd);
    conv_hilo<<<(Dd*FFf + 255)/256, 256>>>(w2, W2hi, W2lo, Dd*FFf);

    build_x_kernel<<<(Mm*Dd/4)/256, 256>>>(feat0, feat1, feat2, pos, X, Xhi, Xlo);

    // QKV = X @ w_in^T + b_in
    gemm_bf16x3<512, 1536, 0><<<dim3(12, Mm/256), 256, GEMM_SMEM>>>(
        Xhi, Xlo, Wihi, Wilo, b_in, nullptr, QKV, nullptr, nullptr);

    attn_kernel<<<Bb*8/4, 128>>>(QKV, Ohi, Olo);

    // Y1 = O @ w_out^T + b_out + X
    gemm_bf16x3<512, 512, 1><<<dim3(4, Mm/256), 256, GEMM_SMEM>>>(
        Ohi, Olo, Wohi, Wolo, b_out, X, Y1, nullptr, nullptr);

    ln_kernel<<<Mm, 128>>>(Y1, ln1g, ln1b, X1, X1hi, X1lo);

    // H = relu(X1 @ w1^T + b1) -> bf16 hi/lo
    gemm_bf16x3<512, 2048, 2><<<dim3(16, Mm/256), 256, GEMM_SMEM>>>(
        X1hi, X1lo, W1hi, W1lo, b1, nullptr, nullptr, Hhi, Hlo);

    // Y2 = H @ w2^T + b2 + X1
    gemm_bf16x3<2048, 512, 1><<<dim3(4, Mm/256), 256, GEMM_SMEM>>>(
        Hhi, Hlo, W2hi, W2lo, b2, X1, Y2, nullptr, nullptr);

    ln_mean_kernel<<<Bb, 128>>>(Y2, ln2g, ln2b, out);
}

// round 6
// speedup vs baseline: 2.5701x; 1.0800x over previous
#include <cuda_runtime.h>
#include <cuda_bf16.h>
#include <cstdint>

constexpr int Bb = 16384, Dd = 512, HDd = 64, FFf = 2048;
constexpr int Mm = Bb * 3;

// scratch
__device__ float g_X [Mm * Dd];
__device__ float g_QKV[(size_t)Mm * 3 * Dd];
__device__ float g_Y1[Mm * Dd];
__device__ float g_X1[Mm * Dd];
__device__ float g_Y2[Mm * Dd];
__device__ __nv_bfloat16 g_Xhi[Mm * Dd], g_Xlo[Mm * Dd];
__device__ __nv_bfloat16 g_Ohi[Mm * Dd], g_Olo[Mm * Dd];
__device__ __nv_bfloat16 g_X1hi[Mm * Dd], g_X1lo[Mm * Dd];
__device__ __nv_bfloat16 g_Hhi[(size_t)Mm * FFf], g_Hlo[(size_t)Mm * FFf];
__device__ __nv_bfloat16 g_Wihi[3 * Dd * Dd], g_Wilo[3 * Dd * Dd];
__device__ __nv_bfloat16 g_Wohi[Dd * Dd],     g_Wolo[Dd * Dd];
__device__ __nv_bfloat16 g_W1hi[FFf * Dd],    g_W1lo[FFf * Dd];
__device__ __nv_bfloat16 g_W2hi[Dd * FFf],    g_W2lo[Dd * FFf];

// ---- helpers ----
__device__ __forceinline__ uint32_t smem_u32(const void* p) {
    uint32_t a;
    asm("{ .reg .u64 t; cvta.to.shared.u64 t, %1; cvt.u32.u64 %0, t; }" : "=r"(a) : "l"(p));
    return a;
}
__device__ __forceinline__ void cp16(uint32_t s, const void* g) {
    asm volatile("cp.async.cg.shared.global [%0], [%1], 16;" :: "r"(s), "l"(g));
}
__device__ __forceinline__ void ldm_x4(uint32_t* r, uint32_t a) {
    asm volatile("ldmatrix.sync.aligned.m8n8.x4.shared.b16 {%0,%1,%2,%3}, [%4];"
                 : "=r"(r[0]), "=r"(r[1]), "=r"(r[2]), "=r"(r[3]) : "r"(a));
}
__device__ __forceinline__ void mma16816(float* c, const uint32_t* a,
                                         uint32_t b0, uint32_t b1) {
    asm volatile(
        "mma.sync.aligned.m16n8k16.row.col.f32.bf16.bf16.f32 "
        "{%0,%1,%2,%3}, {%4,%5,%6,%7}, {%8,%9}, {%0,%1,%2,%3};"
        : "+f"(c[0]), "+f"(c[1]), "+f"(c[2]), "+f"(c[3])
        : "r"(a[0]), "r"(a[1]), "r"(a[2]), "r"(a[3]), "r"(b0), "r"(b1));
}
__device__ __forceinline__ void split2(float x, float y,
                                       __nv_bfloat16* Hi, __nv_bfloat16* Lo, size_t off) {
    __nv_bfloat162 h = __floats2bfloat162_rn(x, y);
    float2 f = __bfloat1622float2(h);
    __nv_bfloat162 l = __floats2bfloat162_rn(x - f.x, y - f.y);
    *reinterpret_cast<__nv_bfloat162*>(Hi + off) = h;
    *reinterpret_cast<__nv_bfloat162*>(Lo + off) = l;
}
__device__ __forceinline__ void split4(float4 o, __nv_bfloat16* Hi, __nv_bfloat16* Lo,
                                       size_t off) {
    split2(o.x, o.y, Hi, Lo, off);
    split2(o.z, o.w, Hi, Lo, off + 2);
}

// ---- merged bf16x3 split mma.sync GEMM: C = (Ahi+Alo)(Bhi+Blo)^T (drop lo*lo) ----
// CTA 128x128, 256 threads, 8 warps (wm 0..3 x wn 0..1), warp tile 32x64, BK=32,
// 2-stage cp.async double buffer -> 2 CTAs/SM. Merged passes with fragment reuse.
// Stage layout: Ahi[0,10240) Alo[10240,20480) Bhi[20480,30720) Blo[30720,40960)
// EPI: 0 = bias->f32 ; 1 = bias+resid->f32 ; 2 = bias+relu->bf16 hi/lo
constexpr int STG_BYTES = 40960;
constexpr int GEMM_SMEM = 2 * STG_BYTES;    // 81920 -> 2 CTAs/SM

template <int K, int N, int EPI>
__global__ __launch_bounds__(256, 2)
void gemm_bf16x3(const __nv_bfloat16* __restrict__ Ahi, const __nv_bfloat16* __restrict__ Alo,
                 const __nv_bfloat16* __restrict__ Bhi, const __nv_bfloat16* __restrict__ Blo,
                 const float* __restrict__ bias, const float* __restrict__ resid,
                 float* __restrict__ Cf,
                 __nv_bfloat16* __restrict__ Chi, __nv_bfloat16* __restrict__ Clo) {
    extern __shared__ char sm_raw[];
    const uint32_t smb = smem_u32(sm_raw);

    const int tid = threadIdx.x, warp = tid >> 5, lane = tid & 31;
    const int m0 = blockIdx.y * 128, n0 = blockIdx.x * 128;
    const int wm = warp >> 1, wn = warp & 1;

    constexpr int NC = K / 32;

    // one stage: 128 A rows + 128 B rows, each row 64B payload in 80B stride, hi+lo
    auto load_chunk = [&](int c) {
        const int kc = c * 32;
        const uint32_t st = smb + (uint32_t)(c & 1) * STG_BYTES;
#pragma unroll
        for (int i = 0; i < 2; i++) {
            const int u = tid + i * 256;           // 0..511: 128 rows x 4 segs
            const int row = u >> 2, seg = u & 3;
            const size_t ga = (size_t)(m0 + row) * K + kc + seg * 8;
            const size_t gb = (size_t)(n0 + row) * K + kc + seg * 8;
            const uint32_t so = st + row * 80 + seg * 16;
            cp16(so,         Ahi + ga);
            cp16(so + 10240, Alo + ga);
            cp16(so + 20480, Bhi + gb);
            cp16(so + 30720, Blo + gb);
        }
        asm volatile("cp.async.commit_group;");
    };

    float acc[2][8][4];
#pragma unroll
    for (int i = 0; i < 2; i++)
#pragma unroll
        for (int j = 0; j < 8; j++)
#pragma unroll
            for (int q = 0; q < 4; q++) acc[i][j][q] = 0.f;

    load_chunk(0);
    if (NC > 1) load_chunk(1);

    const uint32_t a_off = (uint32_t)(wm * 32 + (lane & 15)) * 80 + (lane >> 4) * 16;
    const uint32_t b_off = (uint32_t)(wn * 64 + (lane & 7) + ((lane >> 4) & 1) * 8) * 80
                           + ((lane >> 3) & 1) * 16;

#pragma unroll 1
    for (int c = 0; c < NC; c++) {
        if (c + 1 < NC) { asm volatile("cp.async.wait_group 1;" ::: "memory"); }
        else            { asm volatile("cp.async.wait_group 0;" ::: "memory"); }
        __syncthreads();

        const uint32_t st = smb + (uint32_t)(c & 1) * STG_BYTES;
#pragma unroll
        for (int ks = 0; ks < 2; ks++) {
            uint32_t ah[2][4], bh[4][4], t[4][4];
#pragma unroll
            for (int mt = 0; mt < 2; mt++)
                ldm_x4(ah[mt], st + a_off + (uint32_t)mt * (16 * 80) + ks * 32);
#pragma unroll
            for (int nt = 0; nt < 4; nt++)
                ldm_x4(bh[nt], st + 20480 + b_off + (uint32_t)nt * (16 * 80) + ks * 32);
            // pass 1: Ahi x Bhi
#pragma unroll
            for (int mt = 0; mt < 2; mt++)
#pragma unroll
                for (int nt = 0; nt < 4; nt++) {
                    mma16816(acc[mt][2 * nt],     ah[mt], bh[nt][0], bh[nt][1]);
                    mma16816(acc[mt][2 * nt + 1], ah[mt], bh[nt][2], bh[nt][3]);
                }
            // pass 2: Alo x Bhi
#pragma unroll
            for (int mt = 0; mt < 2; mt++)
                ldm_x4(t[mt], st + 10240 + a_off + (uint32_t)mt * (16 * 80) + ks * 32);
#pragma unroll
            for (int mt = 0; mt < 2; mt++)
#pragma unroll
                for (int nt = 0; nt < 4; nt++) {
                    mma16816(acc[mt][2 * nt],     t[mt], bh[nt][0], bh[nt][1]);
                    mma16816(acc[mt][2 * nt + 1], t[mt], bh[nt][2], bh[nt][3]);
                }
            // pass 3: Ahi x Blo
#pragma unroll
            for (int nt = 0; nt < 4; nt++)
                ldm_x4(t[nt], st + 30720 + b_off + (uint32_t)nt * (16 * 80) + ks * 32);
#pragma unroll
            for (int mt = 0; mt < 2; mt++)
#pragma unroll
                for (int nt = 0; nt < 4; nt++) {
                    mma16816(acc[mt][2 * nt],     ah[mt], t[nt][0], t[nt][1]);
                    mma16816(acc[mt][2 * nt + 1], ah[mt], t[nt][2], t[nt][3]);
                }
        }
        __syncthreads();
        if (c + 2 < NC) load_chunk(c + 2);
    }

    // ---- epilogue ----
#pragma unroll
    for (int mt = 0; mt < 2; mt++) {
        const int r0 = m0 + wm * 32 + mt * 16 + (lane >> 2);
#pragma unroll
        for (int nt = 0; nt < 8; nt++) {
            const int col = n0 + wn * 64 + nt * 8 + 2 * (lane & 3);
            const float2 bb = *reinterpret_cast<const float2*>(bias + col);
            float x0 = acc[mt][nt][0] + bb.x, y0 = acc[mt][nt][1] + bb.y;
            float x1 = acc[mt][nt][2] + bb.x, y1 = acc[mt][nt][3] + bb.y;
            const size_t o0 = (size_t)r0 * N + col;
            const size_t o1 = o0 + (size_t)8 * N;
            if (EPI == 1) {
                const float2 ra = *reinterpret_cast<const float2*>(resid + o0);
                const float2 rb = *reinterpret_cast<const float2*>(resid + o1);
                x0 += ra.x; y0 += ra.y; x1 += rb.x; y1 += rb.y;
            }
            if (EPI == 2) {
                x0 = fmaxf(x0, 0.f); y0 = fmaxf(y0, 0.f);
                x1 = fmaxf(x1, 0.f); y1 = fmaxf(y1, 0.f);
                split2(x0, y0, Chi, Clo, o0);
                split2(x1, y1, Chi, Clo, o1);
            } else {
                *reinterpret_cast<float2*>(Cf + o0) = make_float2(x0, y0);
                *reinterpret_cast<float2*>(Cf + o1) = make_float2(x1, y1);
            }
        }
    }
}

// ---- build X = stack(feat)+pos (+hi/lo) ----
__global__ void build_x_kernel(const float* __restrict__ f0, const float* __restrict__ f1,
                               const float* __restrict__ f2, const float* __restrict__ pos,
                               float* __restrict__ X,
                               __nv_bfloat16* __restrict__ Xhi, __nv_bfloat16* __restrict__ Xlo) {
    int idx = blockIdx.x * blockDim.x + threadIdx.x;
    int m = idx >> 7, c4 = idx & 127;
    int b = m / 3, s = m - b * 3;
    const float* f = (s == 0) ? f0 : ((s == 1) ? f1 : f2);
    const float4 a = *reinterpret_cast<const float4*>(&f[b * Dd + c4 * 4]);
    const float4 p = *reinterpret_cast<const float4*>(&pos[s * Dd + c4 * 4]);
    float4 o = make_float4(a.x + p.x, a.y + p.y, a.z + p.z, a.w + p.w);
    const size_t off = (size_t)m * Dd + c4 * 4;
    *reinterpret_cast<float4*>(&X[off]) = o;
    split4(o, Xhi, Xlo, off);
}

__global__ void conv_hilo(const float* __restrict__ s, __nv_bfloat16* __restrict__ hi,
                          __nv_bfloat16* __restrict__ lo, int n) {
    int i = blockIdx.x * 256 + threadIdx.x;
    if (i < n) {
        float x = s[i];
        __nv_bfloat16 h = __float2bfloat16(x);
        hi[i] = h;
        lo[i] = __float2bfloat16(x - __bfloat162float(h));
    }
}

// ---- attention: one warp per (b,h) ----
__global__ void attn_kernel(const float* __restrict__ QKV,
                            __nv_bfloat16* __restrict__ Ohi, __nv_bfloat16* __restrict__ Olo) {
    const int warp = threadIdx.x >> 5, lane = threadIdx.x & 31;
    const int idx = blockIdx.x * 4 + warp;
    const int b = idx >> 3, h = idx & 7;
    float q[3][2], k[3][2], v[3][2];
#pragma unroll
    for (int s = 0; s < 3; s++) {
        const float* p = QKV + (size_t)(b * 3 + s) * (3 * Dd) + h * HDd;
        q[s][0] = p[lane];          q[s][1] = p[lane + 32];
        k[s][0] = p[Dd + lane];     k[s][1] = p[Dd + lane + 32];
        v[s][0] = p[2*Dd + lane];   v[s][1] = p[2*Dd + lane + 32];
    }
    float sc[3][3];
#pragma unroll
    for (int i = 0; i < 3; i++)
#pragma unroll
        for (int j = 0; j < 3; j++) {
            float p = q[i][0] * k[j][0] + q[i][1] * k[j][1];
#pragma unroll
            for (int o = 16; o > 0; o >>= 1) p += __shfl_xor_sync(~0u, p, o);
            sc[i][j] = p * 0.125f;
        }
#pragma unroll
    for (int i = 0; i < 3; i++) {
        const float mx = fmaxf(fmaxf(sc[i][0], sc[i][1]), sc[i][2]);
        const float e0 = expf(sc[i][0]-mx), e1 = expf(sc[i][1]-mx), e2 = expf(sc[i][2]-mx);
        const float inv = 1.f / (e0 + e1 + e2);
        const float a0 = e0*inv, a1 = e1*inv, a2 = e2*inv;
        const float o0 = a0*v[0][0] + a1*v[1][0] + a2*v[2][0];
        const float o1 = a0*v[0][1] + a1*v[1][1] + a2*v[2][1];
        const size_t op = (size_t)(b * 3 + i) * Dd + h * HDd;
        __nv_bfloat16 h0 = __float2bfloat16(o0), h1 = __float2bfloat16(o1);
        Ohi[op + lane] = h0;      Ohi[op + lane + 32] = h1;
        Olo[op + lane] = __float2bfloat16(o0 - __bfloat162float(h0));
        Olo[op + lane + 32] = __float2bfloat16(o1 - __bfloat162float(h1));
    }
}

// ---- layernorm ----
__device__ __forceinline__ void block_stats(float s, float sq, int t, float* shs, float* shq,
                                            float& mu, float& rs) {
#pragma unroll
    for (int o = 16; o > 0; o >>= 1) {
        s += __shfl_xor_sync(~0u, s, o);
        sq += __shfl_xor_sync(~0u, sq, o);
    }
    const int w = t >> 5;
    if ((t & 31) == 0) { shs[w] = s; shq[w] = sq; }
    __syncthreads();
    const float ts = shs[0]+shs[1]+shs[2]+shs[3], tq = shq[0]+shq[1]+shq[2]+shq[3];
    mu = ts * (1.f/512.f);
    rs = rsqrtf(tq * (1.f/512.f) - mu*mu + 1e-5f);
}

__global__ void ln_kernel(const float* __restrict__ Y, const float* __restrict__ g,
                          const float* __restrict__ bta, float* __restrict__ X,
                          __nv_bfloat16* __restrict__ Xhi, __nv_bfloat16* __restrict__ Xlo) {
    const int row = blockIdx.x, t = threadIdx.x;
    __shared__ float shs[4], shq[4];
    const size_t off = (size_t)row * Dd + t * 4;
    const float4 v = *reinterpret_cast<const float4*>(&Y[off]);
    float mu, rs;
    block_stats(v.x+v.y+v.z+v.w, v.x*v.x+v.y*v.y+v.z*v.z+v.w*v.w, t, shs, shq, mu, rs);
    const float4 gg = *reinterpret_cast<const float4*>(&g[t*4]);
    const float4 bb = *reinterpret_cast<const float4*>(&bta[t*4]);
    float4 o;
    o.x = (v.x-mu)*rs*gg.x + bb.x; o.y = (v.y-mu)*rs*gg.y + bb.y;
    o.z = (v.z-mu)*rs*gg.z + bb.z; o.w = (v.w-mu)*rs*gg.w + bb.w;
    *reinterpret_cast<float4*>(&X[off]) = o;
    split4(o, Xhi, Xlo, off);
}

__global__ void ln_mean_kernel(const float* __restrict__ Y, const float* __restrict__ g,
                               const float* __restrict__ bta, float* __restrict__ out) {
    const int b = blockIdx.x, t = threadIdx.x;
    __shared__ float shs[4], shq[4];
    const float4 gg = *reinterpret_cast<const float4*>(&g[t*4]);
    const float4 bb = *reinterpret_cast<const float4*>(&bta[t*4]);
    float4 acc = make_float4(0.f, 0.f, 0.f, 0.f);
#pragma unroll
    for (int s = 0; s < 3; s++) {
        const float4 v = *reinterpret_cast<const float4*>(&Y[(size_t)(b*3+s)*Dd + t*4]);
        float mu, rs;
        block_stats(v.x+v.y+v.z+v.w, v.x*v.x+v.y*v.y+v.z*v.z+v.w*v.w, t, shs, shq, mu, rs);
        acc.x += (v.x-mu)*rs*gg.x + bb.x; acc.y += (v.y-mu)*rs*gg.y + bb.y;
        acc.z += (v.z-mu)*rs*gg.z + bb.z; acc.w += (v.w-mu)*rs*gg.w + bb.w;
        __syncthreads();
    }
    float4 o = make_float4(acc.x/3.f, acc.y/3.f, acc.z/3.f, acc.w/3.f);
    *reinterpret_cast<float4*>(&out[(size_t)b*Dd + t*4]) = o;
}

// ---- launch ----
extern "C" void kernel_launch(void* const* d_in, const int* in_sizes, int n_in,
                              void* d_out, int out_size) {
    const float* feat0 = (const float*)d_in[0];
    const float* feat1 = (const float*)d_in[1];
    const float* feat2 = (const float*)d_in[2];
    const float* pos   = (const float*)d_in[3];
    const float* w_in  = (const float*)d_in[4];
    const float* b_in  = (const float*)d_in[5];
    const float* w_out = (const float*)d_in[6];
    const float* b_out = (const float*)d_in[7];
    const float* ln1g  = (const float*)d_in[8];
    const float* ln1b  = (const float*)d_in[9];
    const float* w1    = (const float*)d_in[10];
    const float* b1    = (const float*)d_in[11];
    const float* w2    = (const float*)d_in[12];
    const float* b2    = (const float*)d_in[13];
    const float* ln2g  = (const float*)d_in[14];
    const float* ln2b  = (const float*)d_in[15];
    float* out = (float*)d_out;

    float *X, *QKV, *Y1, *X1, *Y2;
    __nv_bfloat16 *Xhi, *Xlo, *Ohi, *Olo, *X1hi, *X1lo, *Hhi, *Hlo;
    __nv_bfloat16 *Wihi, *Wilo, *Wohi, *Wolo, *W1hi, *W1lo, *W2hi, *W2lo;
    cudaGetSymbolAddress((void**)&X, g_X);     cudaGetSymbolAddress((void**)&QKV, g_QKV);
    cudaGetSymbolAddress((void**)&Y1, g_Y1);   cudaGetSymbolAddress((void**)&X1, g_X1);
    cudaGetSymbolAddress((void**)&Y2, g_Y2);
    cudaGetSymbolAddress((void**)&Xhi, g_Xhi);   cudaGetSymbolAddress((void**)&Xlo, g_Xlo);
    cudaGetSymbolAddress((void**)&Ohi, g_Ohi);   cudaGetSymbolAddress((void**)&Olo, g_Olo);
    cudaGetSymbolAddress((void**)&X1hi, g_X1hi); cudaGetSymbolAddress((void**)&X1lo, g_X1lo);
    cudaGetSymbolAddress((void**)&Hhi, g_Hhi);   cudaGetSymbolAddress((void**)&Hlo, g_Hlo);
    cudaGetSymbolAddress((void**)&Wihi, g_Wihi); cudaGetSymbolAddress((void**)&Wilo, g_Wilo);
    cudaGetSymbolAddress((void**)&Wohi, g_Wohi); cudaGetSymbolAddress((void**)&Wolo, g_Wolo);
    cudaGetSymbolAddress((void**)&W1hi, g_W1hi); cudaGetSymbolAddress((void**)&W1lo, g_W1lo);
    cudaGetSymbolAddress((void**)&W2hi, g_W2hi); cudaGetSymbolAddress((void**)&W2lo, g_W2lo);

    cudaFuncSetAttribute(gemm_bf16x3<512, 1536, 0>,
                         cudaFuncAttributeMaxDynamicSharedMemorySize, GEMM_SMEM);
    cudaFuncSetAttribute(gemm_bf16x3<512, 512, 1>,
                         cudaFuncAttributeMaxDynamicSharedMemorySize, GEMM_SMEM);
    cudaFuncSetAttribute(gemm_bf16x3<512, 2048, 2>,
                         cudaFuncAttributeMaxDynamicSharedMemorySize, GEMM_SMEM);
    cudaFuncSetAttribute(gemm_bf16x3<2048, 512, 1>,
                         cudaFuncAttributeMaxDynamicSharedMemorySize, GEMM_SMEM);

    // launch order arranged so our 4th launch is the QKV GEMM (profiling slot)
    conv_hilo<<<(3*Dd*Dd + 255)/256, 256>>>(w_in,  Wihi, Wilo, 3*Dd*Dd);          // 1
    conv_hilo<<<(Dd*Dd + 255)/256, 256>>>(w_out, Wohi, Wolo, Dd*Dd);              // 2
    build_x_kernel<<<(Mm*Dd/4)/256, 256>>>(feat0, feat1, feat2, pos, X, Xhi, Xlo);// 3

    // 4: QKV = X @ w_in^T + b_in
    gemm_bf16x3<512, 1536, 0><<<dim3(12, Mm/128), 256, GEMM_SMEM>>>(
        Xhi, Xlo, Wihi, Wilo, b_in, nullptr, QKV, nullptr, nullptr);

    conv_hilo<<<(FFf*Dd + 255)/256, 256>>>(w1, W1hi, W1lo, FFf*Dd);               // 5
    conv_hilo<<<(Dd*FFf + 255)/256, 256>>>(w2, W2hi, W2lo, Dd*FFf);               // 6

    attn_kernel<<<Bb*8/4, 128>>>(QKV, Ohi, Olo);                                  // 7

    // Y1 = O @ w_out^T + b_out + X
    gemm_bf16x3<512, 512, 1><<<dim3(4, Mm/128), 256, GEMM_SMEM>>>(
        Ohi, Olo, Wohi, Wolo, b_out, X, Y1, nullptr, nullptr);

    ln_kernel<<<Mm, 128>>>(Y1, ln1g, ln1b, X1, X1hi, X1lo);

    // H = relu(X1 @ w1^T + b1) -> bf16 hi/lo
    gemm_bf16x3<512, 2048, 2><<<dim3(16, Mm/128), 256, GEMM_SMEM>>>(
        X1hi, X1lo, W1hi, W1lo, b1, nullptr, nullptr, Hhi, Hlo);

    // Y2 = H @ w2^T + b2 + X1
    gemm_bf16x3<2048, 512, 1><<<dim3(4, Mm/128), 256, GEMM_SMEM>>>(
        Hhi, Hlo, W2hi, W2lo, b2, X1, Y2, nullptr, nullptr);

    ln_mean_kernel<<<Bb, 128>>>(Y2, ln2g, ln2b, out);
}